// round 6
// baseline (speedup 1.0000x reference)
#include <cuda_runtime.h>

#define B_ROWS 16384
#define IN_DIM 2048
#define E_NUM 16
#define KMAX 8

#define TEMP_F 0.7f
#define P_MIN_F 0.92f
#define CLOSE_F 0.82f   // P_MIN - CLOSE_DELTA

#define SC_OFF (B_ROWS * KMAX)          // 131072
#define MK_OFF (2 * B_ROWS * KMAX)      // 262144
#define KV_OFF (3 * B_ROWS * KMAX)      // 393216

typedef unsigned long long u64;

// Packed 2xfp32 FMA (SASS FFMA2) — only reachable via PTX fma.rn.f32x2.
__device__ __forceinline__ u64 ffma2(u64 a, u64 b, u64 c) {
    u64 d;
    asm("fma.rn.f32x2 %0, %1, %2, %3;" : "=l"(d) : "l"(a), "l"(b), "l"(c));
    return d;
}

__global__ __launch_bounds__(128, 3) void dyn_top_gate_kernel(
    const float* __restrict__ x,
    const float* __restrict__ W1,
    const float* __restrict__ W2,
    float* __restrict__ out)
{
    const int warp_id = blockIdx.x * 4 + (threadIdx.x >> 5);
    const int lane = threadIdx.x & 31;
    const int row0 = warp_id * 4;

    // ---------------- GEMM: packed f32x2 accumulators over K-pairs ----------
    // acc[e*4+r] holds a 2-wide partial sum (even/odd K within the lane slice)
    u64 acc[64];
#pragma unroll
    for (int i = 0; i < 64; i++) acc[i] = 0ull;

    const float* xr0 = x + (size_t)(row0 + 0) * IN_DIM;
    const float* xr1 = x + (size_t)(row0 + 1) * IN_DIM;
    const float* xr2 = x + (size_t)(row0 + 2) * IN_DIM;
    const float* xr3 = x + (size_t)(row0 + 3) * IN_DIM;

#pragma unroll 1
    for (int k0 = lane * 4; k0 < IN_DIM; k0 += 128) {
        ulonglong2 xv0 = *reinterpret_cast<const ulonglong2*>(xr0 + k0);
        ulonglong2 xv1 = *reinterpret_cast<const ulonglong2*>(xr1 + k0);
        ulonglong2 xv2 = *reinterpret_cast<const ulonglong2*>(xr2 + k0);
        ulonglong2 xv3 = *reinterpret_cast<const ulonglong2*>(xr3 + k0);
#pragma unroll
        for (int e = 0; e < E_NUM; e++) {
            ulonglong2 w = *reinterpret_cast<const ulonglong2*>(W1 + (size_t)e * IN_DIM + k0);
            acc[e * 4 + 0] = ffma2(w.x, xv0.x, acc[e * 4 + 0]);
            acc[e * 4 + 0] = ffma2(w.y, xv0.y, acc[e * 4 + 0]);
            acc[e * 4 + 1] = ffma2(w.x, xv1.x, acc[e * 4 + 1]);
            acc[e * 4 + 1] = ffma2(w.y, xv1.y, acc[e * 4 + 1]);
            acc[e * 4 + 2] = ffma2(w.x, xv2.x, acc[e * 4 + 2]);
            acc[e * 4 + 2] = ffma2(w.y, xv2.y, acc[e * 4 + 2]);
            acc[e * 4 + 3] = ffma2(w.x, xv3.x, acc[e * 4 + 3]);
            acc[e * 4 + 3] = ffma2(w.y, xv3.y, acc[e * 4 + 3]);
        }
    }

    // ---------------- horizontal pair-collapse + butterfly distribute -------
    // Slot layout chosen so lane l = f + 16*g ends holding (expert f, rows 2g, 2g+1):
    //   s = (r1 e3 e2 e1 e0 r0), and butterfly leaves lane l with slots {2l, 2l+1}.
    float vals[64];
#pragma unroll
    for (int e = 0; e < E_NUM; e++) {
#pragma unroll
        for (int r = 0; r < 4; r++) {
            float2 p = *reinterpret_cast<float2*>(&acc[e * 4 + r]);
            vals[((r & 2) << 4) | (e << 1) | (r & 1)] = p.x + p.y;
        }
    }

#pragma unroll
    for (int off = 16, cnt = 32; off >= 1; off >>= 1, cnt >>= 1) {
        const bool up = (lane & off) != 0;
#pragma unroll
        for (int i = 0; i < cnt; i++) {
            float send = up ? vals[i] : vals[i + cnt];
            float keep = up ? vals[i + cnt] : vals[i];
            float recv = __shfl_xor_sync(0xffffffffu, send, off);
            vals[i] = keep + recv;
        }
    }
    // lane l holds full pre-tanh h for (expert l&15, row0 + 2*(l>>4) + {0,1})

    const int g = lane >> 4;
    const int f = lane & 15;

    const float th0 = tanhf(vals[0]);
    const float th1 = tanhf(vals[1]);

    // per-lane W2 row (expert-out f): logits[b][f] = sum_e h[b][e] * W2[f][e]
    float w2f[E_NUM];
#pragma unroll
    for (int e = 0; e < E_NUM; e++) w2f[e] = __ldg(W2 + f * E_NUM + e);

#pragma unroll
    for (int rr = 0; rr < 2; rr++) {
        const int row = row0 + 2 * g + rr;
        const float tsel = rr ? th1 : th0;

        // gather h[e] for my row: it lives at lane e + 16*g (element rr)
        float logit = 0.f;
#pragma unroll
        for (int e = 0; e < E_NUM; e++) {
            float hv = __shfl_sync(0xffffffffu, tsel, (g << 4) | e);
            logit = fmaf(hv, w2f[e], logit);
        }
        logit = logit / TEMP_F;

        // softmax over the 16-lane segment
        float m = logit;
#pragma unroll
        for (int s = 8; s > 0; s >>= 1)
            m = fmaxf(m, __shfl_xor_sync(0xffffffffu, m, s, 16));

        float ex = expf(logit - m);
        float sum = ex;
#pragma unroll
        for (int s = 8; s > 0; s >>= 1)
            sum += __shfl_xor_sync(0xffffffffu, sum, s, 16);
        float prob = ex / sum;

        // stable descending rank (ties -> smaller expert index first)
        int rank = 0;
#pragma unroll
        for (int g2 = 0; g2 < E_NUM; g2++) {
            float lv = __shfl_sync(0xffffffffu, logit, g2, 16);
            rank += (lv > logit) || (lv == logit && g2 < f);
        }

        // inclusive cumulative prob at my rank; pick p1,p2,p3
        float cum = 0.f, p1 = 0.f, p2 = 0.f, p3 = 0.f;
#pragma unroll
        for (int g2 = 0; g2 < E_NUM; g2++) {
            float pv = __shfl_sync(0xffffffffu, prob, g2, 16);
            int rv = __shfl_sync(0xffffffffu, rank, g2, 16);
            if (rv <= rank) cum += pv;
            if (rv == 0) p1 = pv;
            if (rv == 1) p2 = pv;
            if (rv == 2) p3 = pv;
        }

        // idx_first = #ranks with cum < P_MIN (cum monotone in rank)
        int cnt2 = 0;
#pragma unroll
        for (int g2 = 0; g2 < E_NUM; g2++) {
            float cv = __shfl_sync(0xffffffffu, cum, g2, 16);
            cnt2 += (cv < P_MIN_F);
        }
        if (cnt2 > E_NUM - 1) cnt2 = E_NUM - 1;
        int kv = cnt2 + 1;

        float gap12 = p1 - p2;
        float gap23 = p2 - p3;
        if (p1 >= 0.46f && gap12 >= 0.1f) kv = 1;
        float cum1 = p1 + p2;
        if (kv > 2 && (cum1 >= CLOSE_F || p3 <= 0.12f || gap23 <= 0.03f)) kv = 2;
        kv = max(1, min(3, kv));

        // ---------------- writes ----------------
        if (rank < KMAX) {
            int o = row * KMAX + rank;
            out[o] = (float)f;                                   // top_indices
            out[SC_OFF + o] = (rank < kv) ? prob : 0.f;          // top_scores
            out[MK_OFF + o] = (rank < kv) ? 1.f : 0.f;           // top_mask
        }
        if (rank == 0) out[KV_OFF + row] = (float)kv;            // k_vec
    }
}

extern "C" void kernel_launch(void* const* d_in, const int* in_sizes, int n_in,
                              void* d_out, int out_size) {
    const float* x  = (const float*)d_in[0];
    const float* W1 = (const float*)d_in[1];
    const float* W2 = (const float*)d_in[2];
    float* out = (float*)d_out;

    // 4 rows per warp, 4 warps per block -> 16 rows/block
    const int blocks = B_ROWS / 16;  // 1024
    dyn_top_gate_kernel<<<blocks, 128>>>(x, W1, W2, out);
}

// round 7
// speedup vs baseline: 1.8062x; 1.8062x over previous
#include <cuda_runtime.h>

#define B_ROWS 16384
#define IN_DIM 2048
#define E_NUM 16
#define KMAX 8

#define TEMP_F 0.7f
#define P_MIN_F 0.92f
#define CLOSE_F 0.82f   // P_MIN - CLOSE_DELTA

#define SC_OFF (B_ROWS * KMAX)          // 131072
#define MK_OFF (2 * B_ROWS * KMAX)      // 262144
#define KV_OFF (3 * B_ROWS * KMAX)      // 393216

// FMA body for one 128-wide K slice (4 floats per lane at offset ko)
#define FMA_BODY(v0, v1, v2, v3, ko)                                          \
    {                                                                         \
        const float* wp_ = W1 + (ko);                                         \
        _Pragma("unroll")                                                     \
        for (int e = 0; e < E_NUM; e++) {                                     \
            float4 w = __ldg(reinterpret_cast<const float4*>(                 \
                wp_ + (size_t)e * IN_DIM));                                   \
            acc[e * 4 + 0] = fmaf(w.x, v0.x, acc[e * 4 + 0]);                 \
            acc[e * 4 + 0] = fmaf(w.y, v0.y, acc[e * 4 + 0]);                 \
            acc[e * 4 + 0] = fmaf(w.z, v0.z, acc[e * 4 + 0]);                 \
            acc[e * 4 + 0] = fmaf(w.w, v0.w, acc[e * 4 + 0]);                 \
            acc[e * 4 + 1] = fmaf(w.x, v1.x, acc[e * 4 + 1]);                 \
            acc[e * 4 + 1] = fmaf(w.y, v1.y, acc[e * 4 + 1]);                 \
            acc[e * 4 + 1] = fmaf(w.z, v1.z, acc[e * 4 + 1]);                 \
            acc[e * 4 + 1] = fmaf(w.w, v1.w, acc[e * 4 + 1]);                 \
            acc[e * 4 + 2] = fmaf(w.x, v2.x, acc[e * 4 + 2]);                 \
            acc[e * 4 + 2] = fmaf(w.y, v2.y, acc[e * 4 + 2]);                 \
            acc[e * 4 + 2] = fmaf(w.z, v2.z, acc[e * 4 + 2]);                 \
            acc[e * 4 + 2] = fmaf(w.w, v2.w, acc[e * 4 + 2]);                 \
            acc[e * 4 + 3] = fmaf(w.x, v3.x, acc[e * 4 + 3]);                 \
            acc[e * 4 + 3] = fmaf(w.y, v3.y, acc[e * 4 + 3]);                 \
            acc[e * 4 + 3] = fmaf(w.z, v3.z, acc[e * 4 + 3]);                 \
            acc[e * 4 + 3] = fmaf(w.w, v3.w, acc[e * 4 + 3]);                 \
        }                                                                     \
    }

__global__ __launch_bounds__(256, 2) void dyn_top_gate_kernel(
    const float* __restrict__ x,
    const float* __restrict__ W1,
    const float* __restrict__ W2,
    float* __restrict__ out)
{
    const int warp_id = blockIdx.x * (blockDim.x >> 5) + (threadIdx.x >> 5);
    const int lane = threadIdx.x & 31;
    const int row0 = warp_id * 4;

    float acc[64];
#pragma unroll
    for (int i = 0; i < 64; i++) acc[i] = 0.f;

    const float* xr0 = x + (size_t)(row0 + 0) * IN_DIM;
    const float* xr1 = x + (size_t)(row0 + 1) * IN_DIM;
    const float* xr2 = x + (size_t)(row0 + 2) * IN_DIM;
    const float* xr3 = x + (size_t)(row0 + 3) * IN_DIM;

    // ----- software-pipelined mainloop: 16 bodies, double-buffered x -------
    int off = lane * 4;

    // x is streamed once: __ldcs keeps it out of L1 so W1 stays L1-resident.
    float4 a0 = __ldcs(reinterpret_cast<const float4*>(xr0 + off));
    float4 a1 = __ldcs(reinterpret_cast<const float4*>(xr1 + off));
    float4 a2 = __ldcs(reinterpret_cast<const float4*>(xr2 + off));
    float4 a3 = __ldcs(reinterpret_cast<const float4*>(xr3 + off));
    float4 b0, b1, b2, b3;

#pragma unroll 1
    for (int it = 0; it < 16; it += 2) {
        const int offb = off + 128;          // always < IN_DIM inside loop
        b0 = __ldcs(reinterpret_cast<const float4*>(xr0 + offb));
        b1 = __ldcs(reinterpret_cast<const float4*>(xr1 + offb));
        b2 = __ldcs(reinterpret_cast<const float4*>(xr2 + offb));
        b3 = __ldcs(reinterpret_cast<const float4*>(xr3 + offb));

        FMA_BODY(a0, a1, a2, a3, off);

        const int offa = off + 256;
        if (offa < IN_DIM) {                 // warp-uniform; false only last trip
            a0 = __ldcs(reinterpret_cast<const float4*>(xr0 + offa));
            a1 = __ldcs(reinterpret_cast<const float4*>(xr1 + offa));
            a2 = __ldcs(reinterpret_cast<const float4*>(xr2 + offa));
            a3 = __ldcs(reinterpret_cast<const float4*>(xr3 + offa));
        }

        FMA_BODY(b0, b1, b2, b3, offb);

        off = offa;
    }

    // ----- butterfly distribute-reduce: 64 slots -> 2 fully-reduced / lane --
    // slot s = (r1 e3 e2 e1 e0 r0); lane l=f+16g ends holding slots {2l,2l+1}
    // = pre-tanh h for (expert f, rows row0+2g, row0+2g+1).
    float vals[64];
#pragma unroll
    for (int e = 0; e < E_NUM; e++) {
#pragma unroll
        for (int r = 0; r < 4; r++)
            vals[((r & 2) << 4) | (e << 1) | (r & 1)] = acc[e * 4 + r];
    }

#pragma unroll
    for (int offx = 16, cnt = 32; offx >= 1; offx >>= 1, cnt >>= 1) {
        const bool up = (lane & offx) != 0;
#pragma unroll
        for (int i = 0; i < cnt; i++) {
            float send = up ? vals[i] : vals[i + cnt];
            float keep = up ? vals[i + cnt] : vals[i];
            float recv = __shfl_xor_sync(0xffffffffu, send, offx);
            vals[i] = keep + recv;
        }
    }

    const int g = lane >> 4;
    const int f = lane & 15;

    const float th0 = tanhf(vals[0]);
    const float th1 = tanhf(vals[1]);

    // per-lane W2 row (expert-out f)
    float w2f[E_NUM];
#pragma unroll
    for (int e = 0; e < E_NUM; e++) w2f[e] = __ldg(W2 + f * E_NUM + e);

#pragma unroll
    for (int rr = 0; rr < 2; rr++) {
        const int row = row0 + 2 * g + rr;
        const float tsel = rr ? th1 : th0;

        // gather h[e] for my row: lives at lane e + 16*g
        float logit = 0.f;
#pragma unroll
        for (int e = 0; e < E_NUM; e++) {
            float hv = __shfl_sync(0xffffffffu, tsel, (g << 4) | e);
            logit = fmaf(hv, w2f[e], logit);
        }
        logit = logit / TEMP_F;

        // softmax over the 16-lane segment
        float m = logit;
#pragma unroll
        for (int s = 8; s > 0; s >>= 1)
            m = fmaxf(m, __shfl_xor_sync(0xffffffffu, m, s, 16));

        float ex = expf(logit - m);
        float sum = ex;
#pragma unroll
        for (int s = 8; s > 0; s >>= 1)
            sum += __shfl_xor_sync(0xffffffffu, sum, s, 16);
        float prob = ex / sum;

        // stable descending rank (ties -> smaller expert index first)
        int rank = 0;
#pragma unroll
        for (int g2 = 0; g2 < E_NUM; g2++) {
            float lv = __shfl_sync(0xffffffffu, logit, g2, 16);
            rank += (lv > logit) || (lv == logit && g2 < f);
        }

        // inclusive cumulative prob at my rank; pick p1,p2,p3
        float cum = 0.f, p1 = 0.f, p2 = 0.f, p3 = 0.f;
#pragma unroll
        for (int g2 = 0; g2 < E_NUM; g2++) {
            float pv = __shfl_sync(0xffffffffu, prob, g2, 16);
            int rv = __shfl_sync(0xffffffffu, rank, g2, 16);
            if (rv <= rank) cum += pv;
            if (rv == 0) p1 = pv;
            if (rv == 1) p2 = pv;
            if (rv == 2) p3 = pv;
        }

        // idx_first = #ranks with cum < P_MIN (cum monotone in rank)
        int cnt2 = 0;
#pragma unroll
        for (int g2 = 0; g2 < E_NUM; g2++) {
            float cv = __shfl_sync(0xffffffffu, cum, g2, 16);
            cnt2 += (cv < P_MIN_F);
        }
        if (cnt2 > E_NUM - 1) cnt2 = E_NUM - 1;
        int kv = cnt2 + 1;

        float gap12 = p1 - p2;
        float gap23 = p2 - p3;
        if (p1 >= 0.46f && gap12 >= 0.1f) kv = 1;
        float cum1 = p1 + p2;
        if (kv > 2 && (cum1 >= CLOSE_F || p3 <= 0.12f || gap23 <= 0.03f)) kv = 2;
        kv = max(1, min(3, kv));

        // ----- writes -----
        if (rank < KMAX) {
            int o = row * KMAX + rank;
            out[o] = (float)f;                                   // top_indices
            out[SC_OFF + o] = (rank < kv) ? prob : 0.f;          // top_scores
            out[MK_OFF + o] = (rank < kv) ? 1.f : 0.f;           // top_mask
        }
        if (rank == 0) out[KV_OFF + row] = (float)kv;            // k_vec
    }
}

extern "C" void kernel_launch(void* const* d_in, const int* in_sizes, int n_in,
                              void* d_out, int out_size) {
    const float* x  = (const float*)d_in[0];
    const float* W1 = (const float*)d_in[1];
    const float* W2 = (const float*)d_in[2];
    float* out = (float*)d_out;

    // 4 rows per warp, 8 warps per block -> 32 rows/block
    const int blocks = B_ROWS / 32;  // 512
    dyn_top_gate_kernel<<<blocks, 256>>>(x, W1, W2, out);
}